// round 2
// baseline (speedup 1.0000x reference)
#include <cuda_runtime.h>
#include <math.h>

#define BB 2
#define SS 2048
#define DMODEL 1024
#define NH 16
#define DH 64
#define MM (BB*SS)

// Scratch (device globals: allocation-guard safe). 4 x 16 MB.
__device__ float g_q[BB*NH*SS*DH];
__device__ float g_k[BB*NH*SS*DH];
__device__ float g_v[BB*NH*SS*DH];
__device__ float g_attn[MM*DMODEL];

__device__ __forceinline__ float fex2(float x) {
    float y;
    asm("ex2.approx.ftz.f32 %0, %1;" : "=f"(y) : "f"(x));
    return y;
}

// ---------------------------------------------------------------------------
// GEMM: C[M,N] = A[M,K] * W[N,K]^T   (both row-major, K contiguous)
// Tile 128x128x16, 256 threads, 8x8 per-thread microtile.
// QKV mode: blockIdx.z selects Wq/Wk/Wv, epilogue scatters head-major.
// O mode:   reads g_attn, adds bias, writes dense output.
// ---------------------------------------------------------------------------
template<bool QKV>
__global__ __launch_bounds__(256) void gemm_kernel(
    const float* __restrict__ A,
    const float* __restrict__ W0, const float* __restrict__ W1,
    const float* __restrict__ W2,
    const float* __restrict__ bias, float* __restrict__ Oout)
{
    __shared__ float As[16][128];
    __shared__ float Bs[16][128];

    const float* Ap = QKV ? A : g_attn;
    const float* W = W0;
    if (QKV) {
        if (blockIdx.z == 1) W = W1;
        else if (blockIdx.z == 2) W = W2;
    }

    const int m0 = blockIdx.y * 128;
    const int n0 = blockIdx.x * 128;
    const int tid = threadIdx.x;
    const int tx = tid & 15;   // 0..15 -> n
    const int ty = tid >> 4;   // 0..15 -> m

    float c[8][8];
    #pragma unroll
    for (int i = 0; i < 8; i++)
        #pragma unroll
        for (int j = 0; j < 8; j++) c[i][j] = 0.0f;

    for (int k0 = 0; k0 < DMODEL; k0 += 16) {
        #pragma unroll
        for (int it = 0; it < 2; it++) {
            int f = tid + it * 256;       // 0..511 float4 slots
            int row = f >> 2;             // 0..127
            int c4 = f & 3;               // which float4 within 16 k
            const float4 va = *reinterpret_cast<const float4*>(
                Ap + (size_t)(m0 + row) * DMODEL + k0 + c4 * 4);
            As[c4*4+0][row] = va.x; As[c4*4+1][row] = va.y;
            As[c4*4+2][row] = va.z; As[c4*4+3][row] = va.w;
            const float4 vb = *reinterpret_cast<const float4*>(
                W + (size_t)(n0 + row) * DMODEL + k0 + c4 * 4);
            Bs[c4*4+0][row] = vb.x; Bs[c4*4+1][row] = vb.y;
            Bs[c4*4+2][row] = vb.z; Bs[c4*4+3][row] = vb.w;
        }
        __syncthreads();

        #pragma unroll
        for (int kk = 0; kk < 16; kk++) {
            float a[8], b[8];
            *(float4*)&a[0] = *(float4*)&As[kk][ty*8];
            *(float4*)&a[4] = *(float4*)&As[kk][ty*8+4];
            *(float4*)&b[0] = *(float4*)&Bs[kk][tx*8];
            *(float4*)&b[4] = *(float4*)&Bs[kk][tx*8+4];
            #pragma unroll
            for (int i = 0; i < 8; i++)
                #pragma unroll
                for (int j = 0; j < 8; j++)
                    c[i][j] += a[i] * b[j];
        }
        __syncthreads();
    }

    if (QKV) {
        float* O = (blockIdx.z == 0) ? g_q : (blockIdx.z == 1) ? g_k : g_v;
        #pragma unroll
        for (int i = 0; i < 8; i++) {
            int m = m0 + ty*8 + i;
            int b = m >> 11;          // S = 2048 = 2^11
            int s = m & (SS - 1);
            #pragma unroll
            for (int j = 0; j < 8; j++) {
                int n = n0 + tx*8 + j;
                int h = n >> 6;       // DH = 64
                int d = n & 63;
                O[(((size_t)(b*NH + h)) * SS + s) * DH + d] = c[i][j];
            }
        }
    } else {
        #pragma unroll
        for (int i = 0; i < 8; i++) {
            int m = m0 + ty*8 + i;
            #pragma unroll
            for (int j = 0; j < 8; j++) {
                int n = n0 + tx*8 + j;
                Oout[(size_t)m * DMODEL + n] = c[i][j] + bias[n];
            }
        }
    }
}

// ---------------------------------------------------------------------------
// RoPE (in-place on g_q, g_k). One thread per (bh, s, pair d<32).
// ---------------------------------------------------------------------------
__global__ __launch_bounds__(256) void rope_kernel()
{
    int idx = blockIdx.x * blockDim.x + threadIdx.x;  // < B*H*S*32
    int d  = idx & 31;
    int s  = (idx >> 5) & (SS - 1);
    int bh = idx >> 16;  // 5 + 11 bits
    size_t base = ((size_t)bh * SS + s) * DH;

    // inv_freq = 10000^(-d/32) = 2^(-d * log2(10000)/32)
    const float nl2 = -13.2877123795494f / 32.0f;  // -log2(10000)/32
    float inv_freq = exp2f((float)d * nl2);
    float ang = (float)s * inv_freq;
    float sn, cs;
    sincosf(ang, &sn, &cs);  // accurate range reduction (ang up to ~2047 rad)

    float q1 = g_q[base + d], q2 = g_q[base + d + 32];
    g_q[base + d]      = q1 * cs - q2 * sn;
    g_q[base + d + 32] = q2 * cs + q1 * sn;

    float k1 = g_k[base + d], k2 = g_k[base + d + 32];
    g_k[base + d]      = k1 * cs - k2 * sn;
    g_k[base + d + 32] = k2 * cs + k1 * sn;
}

// ---------------------------------------------------------------------------
// Causal flash attention, fp32. 1 q-row per thread, 128 rows per CTA,
// 32-key tiles. Online softmax in log2 domain.
// Output written to g_attn as [b, s, h*64+d] (ready for the O projection).
// ---------------------------------------------------------------------------
__global__ __launch_bounds__(128) void flash_kernel()
{
    const int bh = blockIdx.x;                    // 0..31
    const int qt = (gridDim.y - 1) - blockIdx.y;  // descending: big tiles first
    const int q0 = qt * 128;
    const int tid = threadIdx.x;
    const int row = q0 + tid;
    const int b = bh >> 4;
    const int h = bh & 15;

    const float* Qb = g_q + (size_t)bh * SS * DH;
    const float* Kb = g_k + (size_t)bh * SS * DH;
    const float* Vb = g_v + (size_t)bh * SS * DH;

    __shared__ float Ks[32 * 64];
    __shared__ float Vs[32 * 64];

    float q[64];
    #pragma unroll
    for (int i = 0; i < 16; i++) {
        float4 v = *reinterpret_cast<const float4*>(Qb + (size_t)row * DH + i * 4);
        q[i*4+0] = v.x; q[i*4+1] = v.y; q[i*4+2] = v.z; q[i*4+3] = v.w;
    }

    float acc[64];
    #pragma unroll
    for (int d = 0; d < 64; d++) acc[d] = 0.0f;
    float m = -INFINITY, l = 0.0f;

    // scale/sqrt(Dh)=1/8, folded with log2(e) so we can use ex2
    const float sc = 0.125f * 1.44269504088896f;

    const int nkt = 4 * (qt + 1);  // covers keys 0 .. q0+127
    for (int kt = 0; kt < nkt; kt++) {
        const int k0 = kt * 32;
        #pragma unroll
        for (int i = 0; i < 4; i++) {
            int f = tid + i * 128;
            reinterpret_cast<float4*>(Ks)[f] =
                reinterpret_cast<const float4*>(Kb + (size_t)k0 * DH)[f];
            reinterpret_cast<float4*>(Vs)[f] =
                reinterpret_cast<const float4*>(Vb + (size_t)k0 * DH)[f];
        }
        __syncthreads();

        float s[32];
        #pragma unroll 8
        for (int j = 0; j < 32; j++) {
            float sum = 0.0f;
            #pragma unroll
            for (int d = 0; d < 64; d++)
                sum += q[d] * Ks[j*64 + d];
            s[j] = (k0 + j <= row) ? sum * sc : -INFINITY;
        }

        float tm = m;
        #pragma unroll
        for (int j = 0; j < 32; j++) tm = fmaxf(tm, s[j]);

        float corr = fex2(m - tm);  // m=-inf first tile -> ex2(-inf)=0
        l *= corr;
        #pragma unroll
        for (int d = 0; d < 64; d++) acc[d] *= corr;

        #pragma unroll 4
        for (int j = 0; j < 32; j++) {
            float p = fex2(s[j] - tm);
            l += p;
            #pragma unroll
            for (int d = 0; d < 64; d++)
                acc[d] += p * Vs[j*64 + d];
        }
        m = tm;
        __syncthreads();
    }

    const float inv = 1.0f / l;
    float* out = g_attn + ((size_t)(b * SS + row)) * DMODEL + h * DH;
    #pragma unroll
    for (int i = 0; i < 16; i++) {
        float4 v;
        v.x = acc[i*4+0] * inv; v.y = acc[i*4+1] * inv;
        v.z = acc[i*4+2] * inv; v.w = acc[i*4+3] * inv;
        *reinterpret_cast<float4*>(out + i * 4) = v;
    }
}

// ---------------------------------------------------------------------------
extern "C" void kernel_launch(void* const* d_in, const int* in_sizes, int n_in,
                              void* d_out, int out_size)
{
    const float* X  = (const float*)d_in[0];
    const float* Wq = (const float*)d_in[1];
    const float* Wk = (const float*)d_in[2];
    const float* Wv = (const float*)d_in[3];
    const float* Wo = (const float*)d_in[4];
    const float* bo = (const float*)d_in[5];
    float* out = (float*)d_out;

    // 1. QKV projections -> head-major scratch
    gemm_kernel<true><<<dim3(8, 32, 3), 256>>>(X, Wq, Wk, Wv, nullptr, nullptr);
    // 2. RoPE in-place on Q, K
    rope_kernel<<<(BB*NH*SS*32) / 256, 256>>>();
    // 3. Causal flash attention -> g_attn [b, s, h*dh]
    flash_kernel<<<dim3(32, 16), 128>>>();
    // 4. Output projection + bias -> d_out
    gemm_kernel<false><<<dim3(8, 32, 1), 256>>>(nullptr, Wo, nullptr, nullptr, bo, out);
}

// round 5
// speedup vs baseline: 1.7338x; 1.7338x over previous
#include <cuda_runtime.h>
#include <cuda_bf16.h>
#include <math.h>
#include <stdint.h>

#define BB 2
#define SS 2048
#define DMODEL 1024
#define NH 16
#define DH 64
#define MM (BB*SS)

// Scratch (device globals: allocation-guard safe).
__device__ float g_q[BB*NH*SS*DH];
__device__ float g_k[BB*NH*SS*DH];
__device__ float g_v[BB*NH*SS*DH];
__device__ float g_attn[MM*DMODEL];

__device__ __forceinline__ float fex2(float x) {
    float y;
    asm("ex2.approx.ftz.f32 %0, %1;" : "=f"(y) : "f"(x));
    return y;
}
__device__ __forceinline__ uint32_t smem_u32(const void* p) {
    uint32_t a;
    asm("{ .reg .u64 t; cvta.to.shared.u64 t, %1; cvt.u32.u64 %0, t; }" : "=r"(a) : "l"(p));
    return a;
}
__device__ __forceinline__ void ldm4(uint32_t* r, uint32_t addr) {
    asm volatile("ldmatrix.sync.aligned.m8n8.x4.shared.b16 {%0,%1,%2,%3}, [%4];"
                 : "=r"(r[0]), "=r"(r[1]), "=r"(r[2]), "=r"(r[3]) : "r"(addr));
}
__device__ __forceinline__ void mma16816(float* c, const uint32_t* a, const uint32_t* b) {
    asm volatile(
        "mma.sync.aligned.m16n8k16.row.col.f32.bf16.bf16.f32 "
        "{%0,%1,%2,%3}, {%4,%5,%6,%7}, {%8,%9}, {%0,%1,%2,%3};"
        : "+f"(c[0]), "+f"(c[1]), "+f"(c[2]), "+f"(c[3])
        : "r"(a[0]), "r"(a[1]), "r"(a[2]), "r"(a[3]), "r"(b[0]), "r"(b[1]));
}
// Split float pair -> packed bf16 hi + packed bf16 residual(lo)
__device__ __forceinline__ uint32_t split2(float x, float y, uint32_t& lop) {
    __nv_bfloat162 h = __floats2bfloat162_rn(x, y);   // .x=low half = x
    float rx = x - __bfloat162float(h.x);
    float ry = y - __bfloat162float(h.y);
    __nv_bfloat162 l = __floats2bfloat162_rn(rx, ry);
    lop = *reinterpret_cast<uint32_t*>(&l);
    return *reinterpret_cast<uint32_t*>(&h);
}
__device__ __forceinline__ void split8(const float4& a, const float4& b,
                                       uint4& hi, uint4& lo) {
    hi.x = split2(a.x, a.y, lo.x);
    hi.y = split2(a.z, a.w, lo.y);
    hi.z = split2(b.x, b.y, lo.z);
    hi.w = split2(b.z, b.w, lo.w);
}

// SMEM tile: 128 rows x 32 bf16, row stride 80 bytes (conflict-free ldmatrix)
#define RSTRIDE 80
#define TILE_BYTES (128 * RSTRIDE)   // 10240

// ---------------------------------------------------------------------------
// HMMA bf16 3x-split GEMM: C[M,N] = A[M,K] * W[N,K]^T  (both row-major).
// 128x128 CTA tile, 8 warps (2m x 4n), warp tile 64x32, K chunks of 32.
// QKV mode scatters head-major; O mode adds bias, writes dense.
// ---------------------------------------------------------------------------
template<bool QKV>
__global__ __launch_bounds__(256) void gemm_hmma(
    const float* __restrict__ A,
    const float* __restrict__ W0, const float* __restrict__ W1,
    const float* __restrict__ W2,
    const float* __restrict__ bias, float* __restrict__ Oout)
{
    __shared__ uint8_t sm[4 * TILE_BYTES];
    const uint32_t sb = smem_u32(sm);
    const uint32_t sAh = sb, sAl = sb + TILE_BYTES;
    const uint32_t sBh = sb + 2*TILE_BYTES, sBl = sb + 3*TILE_BYTES;

    const int tid = threadIdx.x;
    const int lane = tid & 31;
    const int wid = tid >> 5;
    const int warp_m = wid >> 2;     // 0..1 -> 64 rows each
    const int warp_n = wid & 3;      // 0..3 -> 32 cols each

    const float* Ap = QKV ? A : g_attn;
    const float* W = W0;
    if (QKV) {
        if (blockIdx.z == 1) W = W1;
        else if (blockIdx.z == 2) W = W2;
    }
    const int m0 = blockIdx.y * 128;
    const int n0 = blockIdx.x * 128;

    // Load assignment: row pair (lrow, lrow+64), 8 floats at col c8*8.
    const int lrow = tid >> 2;       // 0..63
    const int c8 = tid & 3;          // 0..3

    // ldmatrix lane addressing
    const int aRow = warp_m * 64 + (lane & 15);
    const uint32_t aByte = (uint32_t)((lane >> 4) * 16);
    const int bRow = warp_n * 32 + ((lane >> 4) * 8) + (lane & 7);
    const uint32_t bByte = (uint32_t)(((lane >> 3) & 1) * 16);

    float c[4][4][4];
    #pragma unroll
    for (int i = 0; i < 4; i++)
        #pragma unroll
        for (int j = 0; j < 4; j++)
            #pragma unroll
            for (int e = 0; e < 4; e++) c[i][j][e] = 0.0f;

    for (int ck = 0; ck < 32; ck++) {
        const int k0 = ck * 32;
        // GMEM loads (issued before barrier -> overlap previous MMAs)
        const float* aP0 = Ap + (size_t)(m0 + lrow) * DMODEL + k0 + c8 * 8;
        const float* aP1 = Ap + (size_t)(m0 + lrow + 64) * DMODEL + k0 + c8 * 8;
        const float* bP0 = W + (size_t)(n0 + lrow) * DMODEL + k0 + c8 * 8;
        const float* bP1 = W + (size_t)(n0 + lrow + 64) * DMODEL + k0 + c8 * 8;
        float4 a00 = *(const float4*)aP0, a01 = *(const float4*)(aP0 + 4);
        float4 a10 = *(const float4*)aP1, a11 = *(const float4*)(aP1 + 4);
        float4 b00 = *(const float4*)bP0, b01 = *(const float4*)(bP0 + 4);
        float4 b10 = *(const float4*)bP1, b11 = *(const float4*)(bP1 + 4);

        __syncthreads();  // previous iteration's ldmatrix reads done

        uint4 hi, lo;
        const uint32_t o0 = (uint32_t)(lrow * RSTRIDE + c8 * 16);
        const uint32_t o1 = (uint32_t)((lrow + 64) * RSTRIDE + c8 * 16);
        split8(a00, a01, hi, lo);
        *(uint4*)(sm + (sAh - sb) + o0) = hi;  *(uint4*)(sm + (sAl - sb) + o0) = lo;
        split8(a10, a11, hi, lo);
        *(uint4*)(sm + (sAh - sb) + o1) = hi;  *(uint4*)(sm + (sAl - sb) + o1) = lo;
        split8(b00, b01, hi, lo);
        *(uint4*)(sm + (sBh - sb) + o0) = hi;  *(uint4*)(sm + (sBl - sb) + o0) = lo;
        split8(b10, b11, hi, lo);
        *(uint4*)(sm + (sBh - sb) + o1) = hi;  *(uint4*)(sm + (sBl - sb) + o1) = lo;

        __syncthreads();

        #pragma unroll
        for (int ks = 0; ks < 2; ks++) {
            const uint32_t kByte = (uint32_t)(ks * 32);
            uint32_t ah[4][4], bh[2][4], bl[2][4], al[4][4];
            #pragma unroll
            for (int i = 0; i < 4; i++)
                ldm4(ah[i], sAh + (uint32_t)((aRow + i * 16) * RSTRIDE) + kByte + aByte);
            #pragma unroll
            for (int p = 0; p < 2; p++)
                ldm4(bh[p], sBh + (uint32_t)((bRow + p * 16) * RSTRIDE) + kByte + bByte);
            // product 1: Ah * Bh
            #pragma unroll
            for (int i = 0; i < 4; i++)
                #pragma unroll
                for (int j = 0; j < 4; j++)
                    mma16816(c[i][j], ah[i], &bh[j >> 1][(j & 1) * 2]);
            // product 2: Ah * Bl
            #pragma unroll
            for (int p = 0; p < 2; p++)
                ldm4(bl[p], sBl + (uint32_t)((bRow + p * 16) * RSTRIDE) + kByte + bByte);
            #pragma unroll
            for (int i = 0; i < 4; i++)
                #pragma unroll
                for (int j = 0; j < 4; j++)
                    mma16816(c[i][j], ah[i], &bl[j >> 1][(j & 1) * 2]);
            // product 3: Al * Bh
            #pragma unroll
            for (int i = 0; i < 4; i++)
                ldm4(al[i], sAl + (uint32_t)((aRow + i * 16) * RSTRIDE) + kByte + aByte);
            #pragma unroll
            for (int i = 0; i < 4; i++)
                #pragma unroll
                for (int j = 0; j < 4; j++)
                    mma16816(c[i][j], al[i], &bh[j >> 1][(j & 1) * 2]);
        }
    }

    // Epilogue. Thread owns (m = base + lane/4 [+8], n = base + (lane%4)*2, n+1).
    const int mrow = m0 + warp_m * 64 + (lane >> 2);
    const int ncol = n0 + warp_n * 32 + (lane & 3) * 2;
    #pragma unroll
    for (int i = 0; i < 4; i++) {
        #pragma unroll
        for (int half = 0; half < 2; half++) {
            const int m = mrow + i * 16 + half * 8;
            #pragma unroll
            for (int j = 0; j < 4; j++) {
                const int n = ncol + j * 8;
                float2 v;
                v.x = c[i][j][half * 2 + 0];
                v.y = c[i][j][half * 2 + 1];
                if (QKV) {
                    float* O = (blockIdx.z == 0) ? g_q : (blockIdx.z == 1) ? g_k : g_v;
                    const int b = m >> 11;
                    const int s = m & (SS - 1);
                    const int h = n >> 6, d = n & 63;
                    *reinterpret_cast<float2*>(
                        O + (((size_t)(b * NH + h)) * SS + s) * DH + d) = v;
                } else {
                    v.x += bias[n];
                    v.y += bias[n + 1];
                    *reinterpret_cast<float2*>(Oout + (size_t)m * DMODEL + n) = v;
                }
            }
        }
    }
}

// ---------------------------------------------------------------------------
// RoPE (in-place on g_q, g_k). One thread per (bh, s, pair d<32).
// ---------------------------------------------------------------------------
__global__ __launch_bounds__(256) void rope_kernel()
{
    int idx = blockIdx.x * blockDim.x + threadIdx.x;
    int d  = idx & 31;
    int s  = (idx >> 5) & (SS - 1);
    int bh = idx >> 16;
    size_t base = ((size_t)bh * SS + s) * DH;

    const float nl2 = -13.2877123795494f / 32.0f;  // -log2(10000)/32
    float inv_freq = exp2f((float)d * nl2);
    float ang = (float)s * inv_freq;
    float sn, cs;
    sincosf(ang, &sn, &cs);

    float q1 = g_q[base + d], q2 = g_q[base + d + 32];
    g_q[base + d]      = q1 * cs - q2 * sn;
    g_q[base + d + 32] = q2 * cs + q1 * sn;

    float k1 = g_k[base + d], k2 = g_k[base + d + 32];
    g_k[base + d]      = k1 * cs - k2 * sn;
    g_k[base + d + 32] = k2 * cs + k1 * sn;
}

// ---------------------------------------------------------------------------
// Causal flash attention, fp32 SIMT (unchanged this round).
// ---------------------------------------------------------------------------
__global__ __launch_bounds__(128) void flash_kernel()
{
    const int bh = blockIdx.x;
    const int qt = (gridDim.y - 1) - blockIdx.y;
    const int q0 = qt * 128;
    const int tid = threadIdx.x;
    const int row = q0 + tid;
    const int b = bh >> 4;
    const int h = bh & 15;

    const float* Qb = g_q + (size_t)bh * SS * DH;
    const float* Kb = g_k + (size_t)bh * SS * DH;
    const float* Vb = g_v + (size_t)bh * SS * DH;

    __shared__ float Ks[32 * 64];
    __shared__ float Vs[32 * 64];

    float q[64];
    #pragma unroll
    for (int i = 0; i < 16; i++) {
        float4 v = *reinterpret_cast<const float4*>(Qb + (size_t)row * DH + i * 4);
        q[i*4+0] = v.x; q[i*4+1] = v.y; q[i*4+2] = v.z; q[i*4+3] = v.w;
    }

    float acc[64];
    #pragma unroll
    for (int d = 0; d < 64; d++) acc[d] = 0.0f;
    float m = -INFINITY, l = 0.0f;

    const float sc = 0.125f * 1.44269504088896f;

    const int nkt = 4 * (qt + 1);
    for (int kt = 0; kt < nkt; kt++) {
        const int k0 = kt * 32;
        #pragma unroll
        for (int i = 0; i < 4; i++) {
            int f = tid + i * 128;
            reinterpret_cast<float4*>(Ks)[f] =
                reinterpret_cast<const float4*>(Kb + (size_t)k0 * DH)[f];
            reinterpret_cast<float4*>(Vs)[f] =
                reinterpret_cast<const float4*>(Vb + (size_t)k0 * DH)[f];
        }
        __syncthreads();

        float s[32];
        #pragma unroll 8
        for (int j = 0; j < 32; j++) {
            float sum = 0.0f;
            #pragma unroll
            for (int d = 0; d < 64; d++)
                sum += q[d] * Ks[j*64 + d];
            s[j] = (k0 + j <= row) ? sum * sc : -INFINITY;
        }

        float tm = m;
        #pragma unroll
        for (int j = 0; j < 32; j++) tm = fmaxf(tm, s[j]);

        float corr = fex2(m - tm);
        l *= corr;
        #pragma unroll
        for (int d = 0; d < 64; d++) acc[d] *= corr;

        #pragma unroll 4
        for (int j = 0; j < 32; j++) {
            float p = fex2(s[j] - tm);
            l += p;
            #pragma unroll
            for (int d = 0; d < 64; d++)
                acc[d] += p * Vs[j*64 + d];
        }
        m = tm;
        __syncthreads();
    }

    const float inv = 1.0f / l;
    float* out = g_attn + ((size_t)(b * SS + row)) * DMODEL + h * DH;
    #pragma unroll
    for (int i = 0; i < 16; i++) {
        float4 v;
        v.x = acc[i*4+0] * inv; v.y = acc[i*4+1] * inv;
        v.z = acc[i*4+2] * inv; v.w = acc[i*4+3] * inv;
        *reinterpret_cast<float4*>(out + i * 4) = v;
    }
}

// ---------------------------------------------------------------------------
extern "C" void kernel_launch(void* const* d_in, const int* in_sizes, int n_in,
                              void* d_out, int out_size)
{
    const float* X  = (const float*)d_in[0];
    const float* Wq = (const float*)d_in[1];
    const float* Wk = (const float*)d_in[2];
    const float* Wv = (const float*)d_in[3];
    const float* Wo = (const float*)d_in[4];
    const float* bo = (const float*)d_in[5];
    float* out = (float*)d_out;

    // 1. QKV projections (HMMA bf16 3x-split) -> head-major scratch
    gemm_hmma<true><<<dim3(8, 32, 3), 256>>>(X, Wq, Wk, Wv, nullptr, nullptr);
    // 2. RoPE in-place on Q, K
    rope_kernel<<<(BB*NH*SS*32) / 256, 256>>>();
    // 3. Causal flash attention -> g_attn [b, s, h*dh]
    flash_kernel<<<dim3(32, 16), 128>>>();
    // 4. Output projection + bias -> d_out
    gemm_hmma<false><<<dim3(8, 32, 1), 256>>>(nullptr, Wo, nullptr, nullptr, bo, out);
}

// round 7
// speedup vs baseline: 3.1312x; 1.8060x over previous
#include <cuda_runtime.h>
#include <cuda_bf16.h>
#include <math.h>
#include <stdint.h>

#define BB 2
#define SS 2048
#define DMODEL 1024
#define NH 16
#define DH 64
#define MM (BB*SS)

// Scratch (device globals: allocation-guard safe).
__device__ float g_q[BB*NH*SS*DH];
__device__ float g_k[BB*NH*SS*DH];
__device__ float g_v[BB*NH*SS*DH];
__device__ float g_attn[MM*DMODEL];

__device__ __forceinline__ float fex2(float x) {
    float y;
    asm("ex2.approx.ftz.f32 %0, %1;" : "=f"(y) : "f"(x));
    return y;
}
__device__ __forceinline__ uint32_t smem_u32(const void* p) {
    uint32_t a;
    asm("{ .reg .u64 t; cvta.to.shared.u64 t, %1; cvt.u32.u64 %0, t; }" : "=r"(a) : "l"(p));
    return a;
}
__device__ __forceinline__ void ldm4(uint32_t* r, uint32_t addr) {
    asm volatile("ldmatrix.sync.aligned.m8n8.x4.shared.b16 {%0,%1,%2,%3}, [%4];"
                 : "=r"(r[0]), "=r"(r[1]), "=r"(r[2]), "=r"(r[3]) : "r"(addr));
}
__device__ __forceinline__ void ldm4t(uint32_t* r, uint32_t addr) {
    asm volatile("ldmatrix.sync.aligned.m8n8.x4.trans.shared.b16 {%0,%1,%2,%3}, [%4];"
                 : "=r"(r[0]), "=r"(r[1]), "=r"(r[2]), "=r"(r[3]) : "r"(addr));
}
__device__ __forceinline__ void mma16816(float* c, const uint32_t* a, const uint32_t* b) {
    asm volatile(
        "mma.sync.aligned.m16n8k16.row.col.f32.bf16.bf16.f32 "
        "{%0,%1,%2,%3}, {%4,%5,%6,%7}, {%8,%9}, {%0,%1,%2,%3};"
        : "+f"(c[0]), "+f"(c[1]), "+f"(c[2]), "+f"(c[3])
        : "r"(a[0]), "r"(a[1]), "r"(a[2]), "r"(a[3]), "r"(b[0]), "r"(b[1]));
}
// Split float pair -> packed bf16 hi + packed bf16 residual(lo)
__device__ __forceinline__ uint32_t split2(float x, float y, uint32_t& lop) {
    __nv_bfloat162 h = __floats2bfloat162_rn(x, y);
    float rx = x - __bfloat162float(h.x);
    float ry = y - __bfloat162float(h.y);
    __nv_bfloat162 l = __floats2bfloat162_rn(rx, ry);
    lop = *reinterpret_cast<uint32_t*>(&l);
    return *reinterpret_cast<uint32_t*>(&h);
}
__device__ __forceinline__ void split8(const float4& a, const float4& b,
                                       uint4& hi, uint4& lo) {
    hi.x = split2(a.x, a.y, lo.x);
    hi.y = split2(a.z, a.w, lo.y);
    hi.z = split2(b.x, b.y, lo.z);
    hi.w = split2(b.z, b.w, lo.w);
}

// =========================== GEMM (unchanged, validated) ====================
#define RSTRIDE 80
#define TILE_BYTES (128 * RSTRIDE)

template<bool QKV>
__global__ __launch_bounds__(256) void gemm_hmma(
    const float* __restrict__ A,
    const float* __restrict__ W0, const float* __restrict__ W1,
    const float* __restrict__ W2,
    const float* __restrict__ bias, float* __restrict__ Oout)
{
    __shared__ uint8_t sm[4 * TILE_BYTES];
    const uint32_t sb = smem_u32(sm);
    const uint32_t sAh = sb, sAl = sb + TILE_BYTES;
    const uint32_t sBh = sb + 2*TILE_BYTES, sBl = sb + 3*TILE_BYTES;

    const int tid = threadIdx.x;
    const int lane = tid & 31;
    const int wid = tid >> 5;
    const int warp_m = wid >> 2;
    const int warp_n = wid & 3;

    const float* Ap = QKV ? A : g_attn;
    const float* W = W0;
    if (QKV) {
        if (blockIdx.z == 1) W = W1;
        else if (blockIdx.z == 2) W = W2;
    }
    const int m0 = blockIdx.y * 128;
    const int n0 = blockIdx.x * 128;

    const int lrow = tid >> 2;
    const int c8 = tid & 3;

    const int aRow = warp_m * 64 + (lane & 15);
    const uint32_t aByte = (uint32_t)((lane >> 4) * 16);
    const int bRow = warp_n * 32 + ((lane >> 4) * 8) + (lane & 7);
    const uint32_t bByte = (uint32_t)(((lane >> 3) & 1) * 16);

    float c[4][4][4];
    #pragma unroll
    for (int i = 0; i < 4; i++)
        #pragma unroll
        for (int j = 0; j < 4; j++)
            #pragma unroll
            for (int e = 0; e < 4; e++) c[i][j][e] = 0.0f;

    for (int ck = 0; ck < 32; ck++) {
        const int k0 = ck * 32;
        const float* aP0 = Ap + (size_t)(m0 + lrow) * DMODEL + k0 + c8 * 8;
        const float* aP1 = Ap + (size_t)(m0 + lrow + 64) * DMODEL + k0 + c8 * 8;
        const float* bP0 = W + (size_t)(n0 + lrow) * DMODEL + k0 + c8 * 8;
        const float* bP1 = W + (size_t)(n0 + lrow + 64) * DMODEL + k0 + c8 * 8;
        float4 a00 = *(const float4*)aP0, a01 = *(const float4*)(aP0 + 4);
        float4 a10 = *(const float4*)aP1, a11 = *(const float4*)(aP1 + 4);
        float4 b00 = *(const float4*)bP0, b01 = *(const float4*)(bP0 + 4);
        float4 b10 = *(const float4*)bP1, b11 = *(const float4*)(bP1 + 4);

        __syncthreads();

        uint4 hi, lo;
        const uint32_t o0 = (uint32_t)(lrow * RSTRIDE + c8 * 16);
        const uint32_t o1 = (uint32_t)((lrow + 64) * RSTRIDE + c8 * 16);
        split8(a00, a01, hi, lo);
        *(uint4*)(sm + (sAh - sb) + o0) = hi;  *(uint4*)(sm + (sAl - sb) + o0) = lo;
        split8(a10, a11, hi, lo);
        *(uint4*)(sm + (sAh - sb) + o1) = hi;  *(uint4*)(sm + (sAl - sb) + o1) = lo;
        split8(b00, b01, hi, lo);
        *(uint4*)(sm + (sBh - sb) + o0) = hi;  *(uint4*)(sm + (sBl - sb) + o0) = lo;
        split8(b10, b11, hi, lo);
        *(uint4*)(sm + (sBh - sb) + o1) = hi;  *(uint4*)(sm + (sBl - sb) + o1) = lo;

        __syncthreads();

        #pragma unroll
        for (int ks = 0; ks < 2; ks++) {
            const uint32_t kByte = (uint32_t)(ks * 32);
            uint32_t ah[4][4], bh[2][4], bl[2][4], al[4][4];
            #pragma unroll
            for (int i = 0; i < 4; i++)
                ldm4(ah[i], sAh + (uint32_t)((aRow + i * 16) * RSTRIDE) + kByte + aByte);
            #pragma unroll
            for (int p = 0; p < 2; p++)
                ldm4(bh[p], sBh + (uint32_t)((bRow + p * 16) * RSTRIDE) + kByte + bByte);
            #pragma unroll
            for (int i = 0; i < 4; i++)
                #pragma unroll
                for (int j = 0; j < 4; j++)
                    mma16816(c[i][j], ah[i], &bh[j >> 1][(j & 1) * 2]);
            #pragma unroll
            for (int p = 0; p < 2; p++)
                ldm4(bl[p], sBl + (uint32_t)((bRow + p * 16) * RSTRIDE) + kByte + bByte);
            #pragma unroll
            for (int i = 0; i < 4; i++)
                #pragma unroll
                for (int j = 0; j < 4; j++)
                    mma16816(c[i][j], ah[i], &bl[j >> 1][(j & 1) * 2]);
            #pragma unroll
            for (int i = 0; i < 4; i++)
                ldm4(al[i], sAl + (uint32_t)((aRow + i * 16) * RSTRIDE) + kByte + aByte);
            #pragma unroll
            for (int i = 0; i < 4; i++)
                #pragma unroll
                for (int j = 0; j < 4; j++)
                    mma16816(c[i][j], al[i], &bh[j >> 1][(j & 1) * 2]);
        }
    }

    const int mrow = m0 + warp_m * 64 + (lane >> 2);
    const int ncol = n0 + warp_n * 32 + (lane & 3) * 2;
    #pragma unroll
    for (int i = 0; i < 4; i++) {
        #pragma unroll
        for (int half = 0; half < 2; half++) {
            const int m = mrow + i * 16 + half * 8;
            #pragma unroll
            for (int j = 0; j < 4; j++) {
                const int n = ncol + j * 8;
                float2 v;
                v.x = c[i][j][half * 2 + 0];
                v.y = c[i][j][half * 2 + 1];
                if (QKV) {
                    float* O = (blockIdx.z == 0) ? g_q : (blockIdx.z == 1) ? g_k : g_v;
                    const int b = m >> 11;
                    const int s = m & (SS - 1);
                    const int h = n >> 6, d = n & 63;
                    *reinterpret_cast<float2*>(
                        O + (((size_t)(b * NH + h)) * SS + s) * DH + d) = v;
                } else {
                    v.x += bias[n];
                    v.y += bias[n + 1];
                    *reinterpret_cast<float2*>(Oout + (size_t)m * DMODEL + n) = v;
                }
            }
        }
    }
}

// =========================== RoPE (unchanged) ===============================
__global__ __launch_bounds__(256) void rope_kernel()
{
    int idx = blockIdx.x * blockDim.x + threadIdx.x;
    int d  = idx & 31;
    int s  = (idx >> 5) & (SS - 1);
    int bh = idx >> 16;
    size_t base = ((size_t)bh * SS + s) * DH;

    const float nl2 = -13.2877123795494f / 32.0f;
    float inv_freq = exp2f((float)d * nl2);
    float ang = (float)s * inv_freq;
    float sn, cs;
    sincosf(ang, &sn, &cs);

    float q1 = g_q[base + d], q2 = g_q[base + d + 32];
    g_q[base + d]      = q1 * cs - q2 * sn;
    g_q[base + d + 32] = q2 * cs + q1 * sn;

    float k1 = g_k[base + d], k2 = g_k[base + d + 32];
    g_k[base + d]      = k1 * cs - k2 * sn;
    g_k[base + d + 32] = k2 * cs + k1 * sn;
}

// =========================== Flash attention (HMMA) =========================
// CTA = (bh, 128-row q tile). 8 warps x 16 q-rows. KV tiles of 64.
#define VRS 144                      // smem row stride (bytes), conflict-free
#define FSM (64 * VRS)               // one 64-row tile = 9216 B

__global__ __launch_bounds__(256) void flash_hmma()
{
    __shared__ uint8_t sm[4 * FSM];  // Kh | Kl | Vh | Vl (36 KB)
    const uint32_t sb = smem_u32(sm);
    const uint32_t sKh = sb, sKl = sb + FSM, sVh = sb + 2*FSM, sVl = sb + 3*FSM;

    const int bh = blockIdx.x;
    const int qt = (gridDim.y - 1) - blockIdx.y;   // descending (load balance)
    const int q0 = qt * 128;
    const int tid = threadIdx.x;
    const int lane = tid & 31;
    const int w = tid >> 5;
    const int b = bh >> 4;
    const int h = bh & 15;

    const float* Qb = g_q + (size_t)bh * SS * DH;
    const float* Kb = g_k + (size_t)bh * SS * DH;
    const float* Vb = g_v + (size_t)bh * SS * DH;

    const float sc = 0.125f * 1.44269504088896f;   // 1/sqrt(64) * log2(e)

    // ---- Stage Q (scaled) into smem, then ldmatrix into A-fragments ----
    {
        const int row = tid >> 1;          // 0..127
        const int half = tid & 1;          // 32 floats each
        const float* Qp = Qb + (size_t)(q0 + row) * DH + half * 32;
        uint32_t dst = (uint32_t)(row * VRS + half * 64);
        #pragma unroll
        for (int i = 0; i < 4; i++) {
            float4 x = *reinterpret_cast<const float4*>(Qp + i * 8);
            float4 y = *reinterpret_cast<const float4*>(Qp + i * 8 + 4);
            x.x *= sc; x.y *= sc; x.z *= sc; x.w *= sc;
            y.x *= sc; y.y *= sc; y.z *= sc; y.w *= sc;
            uint4 hi, lo;
            split8(x, y, hi, lo);
            *reinterpret_cast<uint4*>(sm + dst + i * 16) = hi;           // Qh @ sKh
            *reinterpret_cast<uint4*>(sm + 2*FSM + dst + i * 16) = lo;   // Ql @ sVh
        }
    }
    __syncthreads();

    uint32_t qh[4][4], ql[4][4];
    {
        const uint32_t ra = (uint32_t)((w * 16 + (lane & 15)) * VRS) + (uint32_t)((lane >> 4) * 16);
        #pragma unroll
        for (int kb = 0; kb < 4; kb++) {
            ldm4(qh[kb], sKh + ra + (uint32_t)(kb * 32));
            ldm4(ql[kb], sVh + ra + (uint32_t)(kb * 32));
        }
    }

    float o[8][4];
    #pragma unroll
    for (int d = 0; d < 8; d++)
        #pragma unroll
        for (int e = 0; e < 4; e++) o[d][e] = 0.0f;
    float m0 = -INFINITY, m1 = -INFINITY, l0 = 0.0f, l1 = 0.0f;

    // ldmatrix addresses (per-warp constants)
    const uint32_t kAddrBase = (uint32_t)((lane & 7) * VRS + (lane >> 3) * 16);
    // trans-B for V: lanes 0-7 -> k rows 0-7, lanes 8-15 -> k rows 8-15,
    // lanes 16-31 -> same rows, n cols +8 (=+16 bytes)
    const uint32_t vAddrBase = (uint32_t)((lane & 15) * VRS) + (uint32_t)((lane >> 4) * 16);

    const int nkv = 2 * (qt + 1);
    for (int kt = 0; kt < nkv; kt++) {
        const int k0 = kt * 64;
        // ---- cooperative K/V tile load (regs first: overlap prior MMAs) ----
        const int r = tid >> 2;            // 0..63
        const int cc = (tid & 3) * 16;
        float4 kr[4], vr[4];
        {
            const float* Kp = Kb + (size_t)(k0 + r) * DH + cc;
            const float* Vp = Vb + (size_t)(k0 + r) * DH + cc;
            #pragma unroll
            for (int i = 0; i < 4; i++) {
                kr[i] = *reinterpret_cast<const float4*>(Kp + i * 4);
                vr[i] = *reinterpret_cast<const float4*>(Vp + i * 4);
            }
        }
        __syncthreads();   // prior iteration's ldmatrix reads complete
        {
            uint32_t dst = (uint32_t)(r * VRS + (tid & 3) * 32);
            uint4 hi, lo;
            split8(kr[0], kr[1], hi, lo);
            *reinterpret_cast<uint4*>(sm + dst) = hi;
            *reinterpret_cast<uint4*>(sm + FSM + dst) = lo;
            split8(kr[2], kr[3], hi, lo);
            *reinterpret_cast<uint4*>(sm + dst + 16) = hi;
            *reinterpret_cast<uint4*>(sm + FSM + dst + 16) = lo;
            split8(vr[0], vr[1], hi, lo);
            *reinterpret_cast<uint4*>(sm + 2*FSM + dst) = hi;
            *reinterpret_cast<uint4*>(sm + 3*FSM + dst) = lo;
            split8(vr[2], vr[3], hi, lo);
            *reinterpret_cast<uint4*>(sm + 2*FSM + dst + 16) = hi;
            *reinterpret_cast<uint4*>(sm + 3*FSM + dst + 16) = lo;
        }
        __syncthreads();

        // ---- S = Q K^T (3-term split), 16x64 per warp ----
        float s[8][4];
        #pragma unroll
        for (int jb = 0; jb < 8; jb++) {
            s[jb][0] = s[jb][1] = s[jb][2] = s[jb][3] = 0.0f;
            uint32_t khf[8], klf[8];
            const uint32_t ka = kAddrBase + (uint32_t)(jb * 8 * VRS);
            ldm4(&khf[0], sKh + ka);
            ldm4(&khf[4], sKh + ka + 64);
            ldm4(&klf[0], sKl + ka);
            ldm4(&klf[4], sKl + ka + 64);
            #pragma unroll
            for (int kb = 0; kb < 4; kb++) {
                mma16816(s[jb], qh[kb], &khf[kb * 2]);
                mma16816(s[jb], qh[kb], &klf[kb * 2]);
                mma16816(s[jb], ql[kb], &khf[kb * 2]);
            }
        }

        // ---- causal mask (only the 2 diagonal tiles) ----
        if (kt >= nkv - 2) {
            const int r0 = q0 + w * 16 + (lane >> 2);
            const int cb = k0 + (lane & 3) * 2;
            #pragma unroll
            for (int jb = 0; jb < 8; jb++) {
                const int c0 = cb + jb * 8;
                if (c0     > r0)     s[jb][0] = -INFINITY;
                if (c0 + 1 > r0)     s[jb][1] = -INFINITY;
                if (c0     > r0 + 8) s[jb][2] = -INFINITY;
                if (c0 + 1 > r0 + 8) s[jb][3] = -INFINITY;
            }
        }

        // ---- online softmax on fragments ----
        float nm0 = m0, nm1 = m1;
        #pragma unroll
        for (int jb = 0; jb < 8; jb++) {
            nm0 = fmaxf(nm0, fmaxf(s[jb][0], s[jb][1]));
            nm1 = fmaxf(nm1, fmaxf(s[jb][2], s[jb][3]));
        }
        nm0 = fmaxf(nm0, __shfl_xor_sync(0xFFFFFFFF, nm0, 1));
        nm0 = fmaxf(nm0, __shfl_xor_sync(0xFFFFFFFF, nm0, 2));
        nm1 = fmaxf(nm1, __shfl_xor_sync(0xFFFFFFFF, nm1, 1));
        nm1 = fmaxf(nm1, __shfl_xor_sync(0xFFFFFFFF, nm1, 2));
        const float c0 = fex2(m0 - nm0);
        const float c1 = fex2(m1 - nm1);
        m0 = nm0; m1 = nm1;

        float ps0 = 0.0f, ps1 = 0.0f;
        #pragma unroll
        for (int jb = 0; jb < 8; jb++) {
            s[jb][0] = fex2(s[jb][0] - nm0);
            s[jb][1] = fex2(s[jb][1] - nm0);
            s[jb][2] = fex2(s[jb][2] - nm1);
            s[jb][3] = fex2(s[jb][3] - nm1);
            ps0 += s[jb][0] + s[jb][1];
            ps1 += s[jb][2] + s[jb][3];
        }
        ps0 += __shfl_xor_sync(0xFFFFFFFF, ps0, 1);
        ps0 += __shfl_xor_sync(0xFFFFFFFF, ps0, 2);
        ps1 += __shfl_xor_sync(0xFFFFFFFF, ps1, 1);
        ps1 += __shfl_xor_sync(0xFFFFFFFF, ps1, 2);
        l0 = l0 * c0 + ps0;
        l1 = l1 * c1 + ps1;
        #pragma unroll
        for (int d = 0; d < 8; d++) {
            o[d][0] *= c0; o[d][1] *= c0;
            o[d][2] *= c1; o[d][3] *= c1;
        }

        // ---- O += P V (3-term split) ----
        #pragma unroll
        for (int kb = 0; kb < 4; kb++) {
            uint32_t ph[4], pl[4];
            ph[0] = split2(s[2*kb][0],   s[2*kb][1],   pl[0]);
            ph[1] = split2(s[2*kb][2],   s[2*kb][3],   pl[1]);
            ph[2] = split2(s[2*kb+1][0], s[2*kb+1][1], pl[2]);
            ph[3] = split2(s[2*kb+1][2], s[2*kb+1][3], pl[3]);
            const uint32_t va = vAddrBase + (uint32_t)(kb * 16 * VRS);
            #pragma unroll
            for (int dbp = 0; dbp < 4; dbp++) {
                uint32_t vh[4], vl[4];
                ldm4t(vh, sVh + va + (uint32_t)(dbp * 32));
                ldm4t(vl, sVl + va + (uint32_t)(dbp * 32));
                mma16816(o[dbp*2],     ph, &vh[0]);
                mma16816(o[dbp*2],     pl, &vh[0]);
                mma16816(o[dbp*2],     ph, &vl[0]);
                mma16816(o[dbp*2 + 1], ph, &vh[2]);
                mma16816(o[dbp*2 + 1], pl, &vh[2]);
                mma16816(o[dbp*2 + 1], ph, &vl[2]);
            }
        }
    }

    // ---- epilogue: normalize and write to g_attn [b, s, h*64+d] ----
    const float i0 = 1.0f / l0;
    const float i1 = 1.0f / l1;
    const int r0 = q0 + w * 16 + (lane >> 2);
    float* out0 = g_attn + ((size_t)(b * SS + r0)) * DMODEL + h * DH + (lane & 3) * 2;
    float* out1 = out0 + (size_t)8 * DMODEL;
    #pragma unroll
    for (int d = 0; d < 8; d++) {
        float2 v0, v1;
        v0.x = o[d][0] * i0; v0.y = o[d][1] * i0;
        v1.x = o[d][2] * i1; v1.y = o[d][3] * i1;
        *reinterpret_cast<float2*>(out0 + d * 8) = v0;
        *reinterpret_cast<float2*>(out1 + d * 8) = v1;
    }
}

// ---------------------------------------------------------------------------
extern "C" void kernel_launch(void* const* d_in, const int* in_sizes, int n_in,
                              void* d_out, int out_size)
{
    const float* X  = (const float*)d_in[0];
    const float* Wq = (const float*)d_in[1];
    const float* Wk = (const float*)d_in[2];
    const float* Wv = (const float*)d_in[3];
    const float* Wo = (const float*)d_in[4];
    const float* bo = (const float*)d_in[5];
    float* out = (float*)d_out;

    // 1. QKV projections (HMMA bf16 3x-split) -> head-major scratch
    gemm_hmma<true><<<dim3(8, 32, 3), 256>>>(X, Wq, Wk, Wv, nullptr, nullptr);
    // 2. RoPE in-place on Q, K
    rope_kernel<<<(BB*NH*SS*32) / 256, 256>>>();
    // 3. Causal flash attention (HMMA) -> g_attn [b, s, h*dh]
    flash_hmma<<<dim3(32, 16), 256>>>();
    // 4. Output projection + bias -> d_out
    gemm_hmma<false><<<dim3(8, 32, 1), 256>>>(nullptr, Wo, nullptr, nullptr, bo, out);
}